// round 7
// baseline (speedup 1.0000x reference)
#include <cuda_runtime.h>

// Shapes fixed by the problem's setup_inputs.
#define B_     16
#define N_     1024
#define M_     1024
#define CIN_   7
#define C_     8
#define COUT_  16
#define TM_    32      // m-values per block (one per lane of warp 0..7)
#define NG_    128     // n's per warp-group (N/8)
#define THREADS_ 256   // 8 warps = 8 n-groups x 32 m-lanes
#define EPS_   1e-8f

typedef unsigned long long ull;

__device__ __forceinline__ float ex2f(float v) {
    float r; asm("ex2.approx.f32 %0, %1;" : "=f"(r) : "f"(v)); return r;
}
__device__ __forceinline__ ull pack2(float lo, float hi) {
    ull r; asm("mov.b64 %0, {%1, %2};" : "=l"(r) : "f"(lo), "f"(hi)); return r;
}
__device__ __forceinline__ void unpack2(ull v, float& lo, float& hi) {
    asm("mov.b64 {%0, %1}, %2;" : "=f"(lo), "=f"(hi) : "l"(v));
}
// Packed dual-FMA / dual-ADD (Blackwell f32x2).
__device__ __forceinline__ ull fma2(ull a, ull b, ull c) {
    ull d; asm("fma.rn.f32x2 %0, %1, %2, %3;" : "=l"(d) : "l"(a), "l"(b), "l"(c));
    return d;
}
__device__ __forceinline__ ull add2(ull a, ull b) {
    ull d; asm("add.rn.f32x2 %0, %1, %2;" : "=l"(d) : "l"(a), "l"(b));
    return d;
}

// Shared memory (static), with aliasing:
//   [0,      8192)  sxq:  512 ulonglong2 {x_2p,x_2p+1 | q_2p,q_2p+1}
//   [8192,  24576)  syA:  1024 ulonglong2  {1,y0 | y1,y2}
//   [24576, 40960)  syB:  1024 ulonglong2  {y3,y4 | y5,y6}
//   [0,      7168)  sacc: 7 warps x 32 lanes x 8 floats (ALIASES sxq; post-loop)
//   [40960, 41536)  sw (128 floats) + sb (16 floats)
#define SMEM_BYTES (40960 + 576)

__global__ __launch_bounds__(THREADS_, 4)
void convdeepset_kernel(const float* __restrict__ x,     // [B, N]
                        const float* __restrict__ y,     // [B, N, CIN]
                        const float* __restrict__ t,     // [B, M]
                        const float* __restrict__ sigma, // [C]
                        const float* __restrict__ w,     // [COUT, C]
                        const float* __restrict__ bias,  // [COUT]
                        float* __restrict__ out)         // [B, M, COUT]
{
    __shared__ __align__(16) char smem_raw[SMEM_BYTES];
    ulonglong2* sxq  = (ulonglong2*)smem_raw;              // [512]
    ulonglong2* syA  = (ulonglong2*)(smem_raw + 8192);     // [1024]
    ulonglong2* syB  = (ulonglong2*)(smem_raw + 24576);    // [1024]
    float*      sacc = (float*)smem_raw;                   // aliased, post-loop
    float*      sw   = (float*)(smem_raw + 40960);
    float*      sb   = sw + COUT_ * C_;

    const int b    = blockIdx.y;
    const int m0   = blockIdx.x * TM_;
    const int tid  = threadIdx.x;
    const int g    = tid >> 5;        // warp = n-group (0..7)
    const int lane = tid & 31;        // m-lane
    const int m    = m0 + lane;

    if (tid < COUT_ * C_)                sw[tid] = w[tid];
    if (tid >= 128 && tid < 128 + COUT_) sb[tid - 128] = bias[tid - 128];

    // Per-channel exponent coefficient, log2e folded: arg = k2*(x-t)^2
    const float LOG2E = 1.4426950408889634f;
    const float s0 = expf(sigma[0]);
    const float k20 = -(0.5f * LOG2E) / (s0 * s0);
    bool uniform = true;
#pragma unroll
    for (int c = 1; c < C_; c++) {
        float s = expf(sigma[c]);
        uniform &= ((-(0.5f * LOG2E) / (s * s)) == k20);
    }

    const float tm = t[b * M_ + m];
    // k2*(x-t)^2 = (k2*x^2) + U*x + T
    const float U = -2.0f * k20 * tm;
    const float T = k20 * tm * tm;
    const ull UU = pack2(U, U), TT = pack2(T, T);

    const float* xb  = x + b * N_;
    const float* ybp = y + (size_t)b * N_ * CIN_;

    // ---- Cooperative tile load: each thread loads 4 n's ----
    {
        float* sxqF = (float*)sxq;
#pragma unroll
        for (int r = 0; r < 4; r++) {
            const int n = tid + r * THREADS_;
            const float xv = xb[n];
            const int p = n >> 1, hhalf = n & 1;
            sxqF[p * 4 + hhalf]     = xv;
            sxqF[p * 4 + 2 + hhalf] = k20 * xv * xv;
            const float* yp = ybp + (size_t)n * CIN_;
            float y0 = yp[0], y1 = yp[1], y2 = yp[2], y3 = yp[3];
            float y4 = yp[4], y5 = yp[5], y6 = yp[6];
            syA[n] = make_ulonglong2(pack2(1.0f, y0), pack2(y1, y2));
            syB[n] = make_ulonglong2(pack2(y3, y4), pack2(y5, y6));
        }
    }
    __syncthreads();

    ull acc0 = 0ull, acc1 = 0ull, acc2 = 0ull, acc3 = 0ull;

    const ulonglong2* xq = sxq + g * (NG_ / 2);
    const ulonglong2* yA = syA + g * NG_;
    const ulonglong2* yB = syB + g * NG_;

    if (uniform) {
        // Fast path: 2 n's per step; all smem reads are warp-broadcast.
#pragma unroll 2
        for (int jj = 0; jj < NG_ / 2; jj++) {
            ulonglong2 v = xq[jj];                    // {x0,x1 | q0,q1}
            ull args = add2(fma2(UU, v.x, TT), v.y);
            float f0, f1; unpack2(args, f0, f1);
            float e0 = ex2f(f0), e1 = ex2f(f1);
            ull ee0 = pack2(e0, e0);
            ulonglong2 A0 = yA[2 * jj], B0 = yB[2 * jj];
            acc0 = fma2(A0.x, ee0, acc0);
            acc1 = fma2(A0.y, ee0, acc1);
            acc2 = fma2(B0.x, ee0, acc2);
            acc3 = fma2(B0.y, ee0, acc3);
            ull ee1 = pack2(e1, e1);
            ulonglong2 A1 = yA[2 * jj + 1], B1 = yB[2 * jj + 1];
            acc0 = fma2(A1.x, ee1, acc0);
            acc1 = fma2(A1.y, ee1, acc1);
            acc2 = fma2(B1.x, ee1, acc2);
            acc3 = fma2(B1.y, ee1, acc3);
        }
    } else {
        // General path (arbitrary sigma): per-channel exponent.
        float k2[C_];
#pragma unroll
        for (int c = 0; c < C_; c++) {
            float s = expf(sigma[c]);
            k2[c] = -(0.5f * LOG2E) / (s * s);
        }
        float accs[C_];
#pragma unroll
        for (int c = 0; c < C_; c++) accs[c] = 0.0f;
        const float* xqF = (const float*)xq;
        for (int j = 0; j < NG_; j++) {
            const int p = j >> 1, hhalf = j & 1;
            const float xv = xqF[p * 4 + hhalf];
            const float dd = xv - tm, dd2 = dd * dd;
            ulonglong2 ya = yA[j], yb = yB[j];
            float yv[C_];
            unpack2(ya.x, yv[0], yv[1]);
            unpack2(ya.y, yv[2], yv[3]);
            unpack2(yb.x, yv[4], yv[5]);
            unpack2(yb.y, yv[6], yv[7]);
#pragma unroll
            for (int c = 0; c < C_; c++)
                accs[c] = fmaf(yv[c], ex2f(k2[c] * dd2), accs[c]);
        }
        acc0 = pack2(accs[0], accs[1]);
        acc1 = pack2(accs[2], accs[3]);
        acc2 = pack2(accs[4], accs[5]);
        acc3 = pack2(accs[6], accs[7]);
    }

    // ---- Reduce the 8 warp partials (sacc aliases the dead sxq tile) ----
    __syncthreads();
    if (g > 0) {
        ulonglong2* d2 = (ulonglong2*)(sacc + ((g - 1) * 32 + lane) * C_);
        d2[0] = make_ulonglong2(acc0, acc1);
        d2[1] = make_ulonglong2(acc2, acc3);
    }
    __syncthreads();
    if (g == 0) {
#pragma unroll
        for (int p = 0; p < 7; p++) {
            const ulonglong2* s2 = (const ulonglong2*)(sacc + (p * 32 + lane) * C_);
            ulonglong2 r0 = s2[0], r1 = s2[1];
            acc0 = add2(acc0, r0.x);
            acc1 = add2(acc1, r0.y);
            acc2 = add2(acc2, r1.x);
            acc3 = add2(acc3, r1.y);
        }

        float a[C_];
        unpack2(acc0, a[0], a[1]);
        unpack2(acc1, a[2], a[3]);
        unpack2(acc2, a[4], a[5]);
        unpack2(acc3, a[6], a[7]);

        float density = a[0];
        float inv = 1.0f / (density + EPS_);
        float feats[C_];
        feats[0] = density;
#pragma unroll
        for (int c = 1; c < C_; c++) feats[c] = a[c] * inv;

        float* op = out + ((size_t)(b * M_ + m)) * COUT_;
#pragma unroll
        for (int og = 0; og < 4; og++) {
            float rr[4];
#pragma unroll
            for (int k = 0; k < 4; k++) {
                const int o = og * 4 + k;
                float s = sb[o];
#pragma unroll
                for (int c = 0; c < C_; c++)
                    s = fmaf(sw[o * C_ + c], feats[c], s);
                rr[k] = s;
            }
            *(float4*)(op + og * 4) = make_float4(rr[0], rr[1], rr[2], rr[3]);
        }
    }
}

extern "C" void kernel_launch(void* const* d_in, const int* in_sizes, int n_in,
                              void* d_out, int out_size) {
    (void)in_sizes; (void)n_in; (void)out_size;
    const float* x     = (const float*)d_in[0];
    const float* y     = (const float*)d_in[1];
    const float* t     = (const float*)d_in[2];
    const float* sigma = (const float*)d_in[3];
    const float* w     = (const float*)d_in[4];
    const float* bias  = (const float*)d_in[5];
    float* out = (float*)d_out;

    dim3 grid(M_ / TM_, B_);
    convdeepset_kernel<<<grid, THREADS_>>>(x, y, t, sigma, w, bias, out);
}